// round 15
// baseline (speedup 1.0000x reference)
#include <cuda_runtime.h>
#include <cuda_fp16.h>
#include <math.h>
#include <stdint.h>

#define NN 100000
#define NE 1600000
#define DF 256
#define NBLK ((NN + 255) / 256)   // 391

// ---------------- scratch (static device globals; no allocation) ----------------
__device__ int   g_deg[NN];
__device__ float g_invdeg[NN];
__device__ int   g_rowptr[NN + 1];
__device__ int   g_cursor[NN];
__device__ int   g_blksum[512];
__device__ int   g_esrc[NE];
__device__ float g_p[NN];
__device__ float g_q[NN];
__device__ __align__(16) __half g_zy[(size_t)NN * 512];   // [z(256) | y(256)] fp16 per node
__device__ __align__(16) __half g_x[(size_t)NN * DF];     // x fp16
__device__ __align__(16) __half g_wt[256 * 512];          // [K=256][N=512] = [Ws1 | Wn1] fp16

// ---------------- helpers ----------------
__device__ __forceinline__ uint32_t s2u(const void* p) {
    uint32_t a;
    asm("{ .reg .u64 t; cvta.to.shared.u64 t, %1; cvt.u32.u64 %0, t; }"
        : "=r"(a) : "l"(p));
    return a;
}

__device__ __forceinline__ void cpa16(uint32_t dst, const void* src) {
    asm volatile("cp.async.cg.shared.global [%0], [%1], 16;" :: "r"(dst), "l"(src));
}
#define CP_COMMIT() asm volatile("cp.async.commit_group;" ::: "memory")
#define CP_WAIT2()  asm volatile("cp.async.wait_group 2;" ::: "memory")
#define CP_WAIT1()  asm volatile("cp.async.wait_group 1;" ::: "memory")
#define CP_WAIT0()  asm volatile("cp.async.wait_group 0;" ::: "memory")

#define LDSM4(r, addr) \
    asm volatile("ldmatrix.sync.aligned.m8n8.x4.shared.b16 {%0,%1,%2,%3}, [%4];" \
        : "=r"((r)[0]), "=r"((r)[1]), "=r"((r)[2]), "=r"((r)[3]) : "r"(addr))

#define LDSM4T(r, addr) \
    asm volatile("ldmatrix.sync.aligned.m8n8.x4.trans.shared.b16 {%0,%1,%2,%3}, [%4];" \
        : "=r"((r)[0]), "=r"((r)[1]), "=r"((r)[2]), "=r"((r)[3]) : "r"(addr))

__device__ __forceinline__ void mma_f16(float* c, const uint32_t* a, const uint32_t* b) {
    asm volatile(
        "mma.sync.aligned.m16n8k16.row.col.f32.f16.f16.f32 "
        "{%0,%1,%2,%3}, {%4,%5,%6,%7}, {%8,%9}, {%0,%1,%2,%3};"
        : "+f"(c[0]), "+f"(c[1]), "+f"(c[2]), "+f"(c[3])
        : "r"(a[0]), "r"(a[1]), "r"(a[2]), "r"(a[3]), "r"(b[0]), "r"(b[1]));
}

// ---------------- zero deg (stream 0, before hist) ----------------
__global__ void k_zero() {
    int i = blockIdx.x * 256 + threadIdx.x;
    if (i < NN) g_deg[i] = 0;
}

// ---------------- X -> fp16 ----------------
__global__ void k_prepx(const float* __restrict__ x) {
    int gi = blockIdx.x * 256 + threadIdx.x;        // NN*64 threads, 4 floats each
    float4 v = ((const float4*)x)[gi];
    uint2 o;
    __half2 p0 = __floats2half2_rn(v.x, v.y);
    __half2 p1 = __floats2half2_rn(v.z, v.w);
    o.x = *reinterpret_cast<uint32_t*>(&p0);
    o.y = *reinterpret_cast<uint32_t*>(&p1);
    ((uint2*)g_x)[gi] = o;
}

// ---------------- weights -> fp16 [K=256][N=512] = [Ws1 | Wn1] ----------------
__global__ void k_prepw(const float* __restrict__ Ws, const float* __restrict__ Wn) {
    int idx = blockIdx.x * 256 + threadIdx.x;   // 512 blocks -> 131072
    int k = idx >> 9;
    int n = idx & 511;
    float w = (n < 256) ? Ws[(size_t)k * 256 + n] : Wn[(size_t)k * 256 + (n - 256)];
    g_wt[idx] = __float2half_rn(w);
}

// ---------------- CSR build ----------------
__global__ void k_hist(const int* __restrict__ dst) {
    int e = blockIdx.x * 256 + threadIdx.x;
    if (e < NE) atomicAdd(&g_deg[dst[e]], 1);
}

__global__ void k_scanA() {
    __shared__ int sh[256];
    int b = blockIdx.x, t = threadIdx.x;
    int i = b * 256 + t;
    int v = (i < NN) ? g_deg[i] : 0;
    sh[t] = v;
    __syncthreads();
#pragma unroll
    for (int o = 1; o < 256; o <<= 1) {
        int x = (t >= o) ? sh[t - o] : 0;
        __syncthreads();
        sh[t] += x;
        __syncthreads();
    }
    if (i < NN) g_rowptr[i] = sh[t] - v;
    if (t == 255) g_blksum[b] = sh[255];
}

// scanC with inlined block-sum prefix (replaces scanB+scanC)
__global__ void k_scanC() {
    __shared__ int red[256];
    int b = blockIdx.x, t = threadIdx.x;

    // sum of g_blksum[0..b-1]
    int part = 0;
    for (int j = t; j < b; j += 256) part += g_blksum[j];
    red[t] = part;
    __syncthreads();
#pragma unroll
    for (int o = 128; o > 0; o >>= 1) {
        if (t < o) red[t] += red[t + o];
        __syncthreads();
    }
    int off = red[0];

    int i = b * 256 + t;
    if (i < NN) {
        int r = g_rowptr[i] + off;
        g_rowptr[i] = r;
        g_cursor[i] = r;
        int d = g_deg[i];
        g_invdeg[i] = 1.0f / (float)(d > 1 ? d : 1);
    }
    if (i == 0) g_rowptr[NN] = NE;
}

__global__ void k_scatter(const int* __restrict__ src, const int* __restrict__ dst) {
    int e = blockIdx.x * 256 + threadIdx.x;
    if (e < NE) {
        int d = dst[e];
        int p = atomicAdd(&g_cursor[d], 1);
        g_esrc[p] = src[e];
    }
}

// ---------------- GEMM: [z|y] = x @ [Ws1|Wn1] (+b1 on z), fp16 in/out ----------------
// tile 128(M) x 128(N), K=256 in 4 chunks of 64; 3-stage cp.async; grid (4, 782)
#define AST 72    // As row stride (fp16 elems): 64 + 8 pad
#define BST 136   // Bs row stride (fp16 elems)
#define OFF_A 0
#define OFF_B 18432                    // 128*72*2
#define ST_BYTES 35840                 // 18432 + 64*136*2
#define GM_SMEM (3 * ST_BYTES + 512)   // 108032

__global__ __launch_bounds__(256) void k_gemm2(const float* __restrict__ bias) {
    extern __shared__ char dsm[];
    uint32_t sbase = s2u(dsm);
    float* sbb = (float*)(dsm + 3 * ST_BYTES);

    int tid = threadIdx.x;
    int wid = tid >> 5, lane = tid & 31;
    int brow = blockIdx.y * 128;
    int bcol = blockIdx.x * 128;
    int wm = wid & 3, wn = wid >> 2;

    if (tid < 128)
        sbb[tid] = (bcol < 256) ? __ldg(bias + bcol + tid) : 0.f;

    float c[2][8][4];
#pragma unroll
    for (int mt = 0; mt < 2; ++mt)
#pragma unroll
        for (int nt = 0; nt < 8; ++nt)
#pragma unroll
            for (int j = 0; j < 4; ++j) c[mt][nt][j] = 0.f;

    // A copy map: row = tid>>1 (0..127), 32-col half; B copy map: k-row = tid>>2 (0..63), 32-col quarter
    int arow = tid >> 1;
    int acol = (tid & 1) * 32;
    int grow = brow + arow;
    if (grow >= NN) grow = NN - 1;
    int bkr = tid >> 2;
    int bnc = (tid & 3) * 32;

    uint32_t da = OFF_A + (uint32_t)(arow * AST + acol) * 2;
    uint32_t db = OFF_B + (uint32_t)(bkr * BST + bnc) * 2;

    auto issue = [&](int ch, int s) {
        int ka = ch * 64;
        uint32_t st = sbase + (uint32_t)s * ST_BYTES;
        size_t aoff = (size_t)grow * 256 + ka + acol;
#pragma unroll
        for (int i = 0; i < 4; ++i)
            cpa16(st + da + i * 16, g_x + aoff + i * 8);
        size_t boff = (size_t)(ka + bkr) * 512 + bcol + bnc;
#pragma unroll
        for (int i = 0; i < 4; ++i)
            cpa16(st + db + i * 16, g_wt + boff + i * 8);
        CP_COMMIT();
    };

    issue(0, 0);
    issue(1, 1);
    issue(2, 2);

#pragma unroll 1
    for (int ch = 0; ch < 4; ++ch) {
        if (ch <= 1) CP_WAIT2();
        else if (ch == 2) CP_WAIT1();
        else CP_WAIT0();
        __syncthreads();

        uint32_t st = sbase + (uint32_t)(ch % 3) * ST_BYTES;
        uint32_t ab = st + OFF_A, bb = st + OFF_B;

#pragma unroll
        for (int ks = 0; ks < 4; ++ks) {
            int kk = ks * 16;
            uint32_t af[2][4];
#pragma unroll
            for (int mt = 0; mt < 2; ++mt) {
                int m0 = wm * 32 + mt * 16;
                uint32_t ao = (uint32_t)((m0 + (lane & 15)) * AST + kk + (lane >> 4) * 8) * 2;
                LDSM4(af[mt], ab + ao);
            }
            uint32_t bf[8][2];
#pragma unroll
            for (int nq = 0; nq < 4; ++nq) {
                int n0 = wn * 64 + nq * 16;
                uint32_t bo = (uint32_t)((kk + (lane & 15)) * BST + n0 + (lane >> 4) * 8) * 2;
                uint32_t r[4];
                LDSM4T(r, bb + bo);
                bf[nq * 2][0] = r[0]; bf[nq * 2][1] = r[1];
                bf[nq * 2 + 1][0] = r[2]; bf[nq * 2 + 1][1] = r[3];
            }
#pragma unroll
            for (int mt = 0; mt < 2; ++mt)
#pragma unroll
                for (int nt = 0; nt < 8; ++nt)
                    mma_f16(c[mt][nt], af[mt], bf[nt]);
        }

        // only one refill needed (prologue covered 3 of 4 chunks)
        if (ch == 0) {
            __syncthreads();          // all warps done reading stage 0
            issue(3, 0);
        }
    }

    // epilogue: +bias (z half only), fp16 store to g_zy
#pragma unroll
    for (int mt = 0; mt < 2; ++mt) {
#pragma unroll
        for (int rh = 0; rh < 2; ++rh) {
            int row = brow + wm * 32 + mt * 16 + (lane >> 2) + rh * 8;
            if (row >= NN) continue;
#pragma unroll
            for (int nt = 0; nt < 8; ++nt) {
                int lcol = wn * 64 + nt * 8 + (lane & 3) * 2;
                float v0 = c[mt][nt][rh * 2 + 0] + sbb[lcol];
                float v1 = c[mt][nt][rh * 2 + 1] + sbb[lcol + 1];
                __half2 hv = __floats2half2_rn(v0, v1);
                *(__half2*)(g_zy + (size_t)row * 512 + bcol + lcol) = hv;
            }
        }
    }
}

// ---------------- fused: mean-gather(y fp16) + z + sigmoid + layer-2 dots ----------------
__global__ __launch_bounds__(256) void k_fused(const float* __restrict__ Ws2,
                                               const float* __restrict__ Wn2) {
    __shared__ float sw[256], sn[256];
    int t = threadIdx.x;
    sw[t] = Ws2[t];
    sn[t] = Wn2[t];
    __syncthreads();

    int warp = t >> 5, lane = t & 31;
    int node = blockIdx.x * 8 + warp;
    if (node >= NN) return;

    int beg = g_rowptr[node];
    int end = g_rowptr[node + 1];
    int c0 = lane * 8;

    float acc[8];
#pragma unroll
    for (int i = 0; i < 8; ++i) acc[i] = 0.f;

    const __half* Y = g_zy;
    int e = beg;
    for (; e + 1 < end; e += 2) {
        int s0 = g_esrc[e];
        int s1 = g_esrc[e + 1];
        uint4 u0 = *(const uint4*)(Y + (size_t)s0 * 512 + 256 + c0);
        uint4 u1 = *(const uint4*)(Y + (size_t)s1 * 512 + 256 + c0);
        const __half2* p0 = (const __half2*)&u0;
        const __half2* p1 = (const __half2*)&u1;
#pragma unroll
        for (int i = 0; i < 4; ++i) {
            float2 f0 = __half22float2(p0[i]);
            float2 f1 = __half22float2(p1[i]);
            acc[i * 2]     += f0.x + f1.x;
            acc[i * 2 + 1] += f0.y + f1.y;
        }
    }
    if (e < end) {
        int s0 = g_esrc[e];
        uint4 u0 = *(const uint4*)(Y + (size_t)s0 * 512 + 256 + c0);
        const __half2* p0 = (const __half2*)&u0;
#pragma unroll
        for (int i = 0; i < 4; ++i) {
            float2 f0 = __half22float2(p0[i]);
            acc[i * 2]     += f0.x;
            acc[i * 2 + 1] += f0.y;
        }
    }

    float id = g_invdeg[node];
    uint4 uz = *(const uint4*)(Y + (size_t)node * 512 + c0);
    const __half2* pz = (const __half2*)&uz;

    float q = 0.f, p = 0.f;
#pragma unroll
    for (int i = 0; i < 4; ++i) {
        float2 z = __half22float2(pz[i]);
        float v0 = z.x + acc[i * 2] * id;
        float v1 = z.y + acc[i * 2 + 1] * id;
        float h0 = 1.f / (1.f + __expf(-v0));
        float h1 = 1.f / (1.f + __expf(-v1));
        q += h0 * sw[c0 + i * 2] + h1 * sw[c0 + i * 2 + 1];
        p += h0 * sn[c0 + i * 2] + h1 * sn[c0 + i * 2 + 1];
    }
#pragma unroll
    for (int o = 16; o > 0; o >>= 1) {
        q += __shfl_down_sync(0xffffffffu, q, o);
        p += __shfl_down_sync(0xffffffffu, p, o);
    }
    if (lane == 0) {
        g_q[node] = q;
        g_p[node] = p;
    }
}

// ---------------- layer 2b: scalar mean-aggregate + combine ----------------
__global__ void k_agg_scalar(const float* __restrict__ b2, float* __restrict__ out) {
    int n = blockIdx.x * 256 + threadIdx.x;
    if (n >= NN) return;
    int beg = g_rowptr[n];
    int end = g_rowptr[n + 1];
    float s0 = 0.f, s1 = 0.f, s2 = 0.f, s3 = 0.f;
    int e = beg;
    for (; e + 3 < end; e += 4) {
        s0 += g_p[g_esrc[e]];
        s1 += g_p[g_esrc[e + 1]];
        s2 += g_p[g_esrc[e + 2]];
        s3 += g_p[g_esrc[e + 3]];
    }
    for (; e < end; ++e) s0 += g_p[g_esrc[e]];
    float s = (s0 + s1) + (s2 + s3);
    out[n] = g_q[n] + b2[0] + s * g_invdeg[n];
}

// ---------------- launch ----------------
extern "C" void kernel_launch(void* const* d_in, const int* in_sizes, int n_in,
                              void* d_out, int out_size) {
    const float* x   = (const float*)d_in[0];
    const int*   src = (const int*)d_in[1];
    const int*   dst = (const int*)d_in[2];
    const float* Ws1 = (const float*)d_in[3];
    const float* Wn1 = (const float*)d_in[4];
    const float* b1  = (const float*)d_in[5];
    const float* Ws2 = (const float*)d_in[6];
    const float* Wn2 = (const float*)d_in[7];
    const float* b2  = (const float*)d_in[8];
    float* out = (float*)d_out;

    static cudaStream_t s1 = nullptr;
    static cudaEvent_t evFork = nullptr, evJoin = nullptr;
    if (!s1) {
        cudaStreamCreateWithFlags(&s1, cudaStreamNonBlocking);
        cudaEventCreateWithFlags(&evFork, cudaEventDisableTiming);
        cudaEventCreateWithFlags(&evJoin, cudaEventDisableTiming);
        cudaFuncSetAttribute(k_gemm2, cudaFuncAttributeMaxDynamicSharedMemorySize, GM_SMEM);
    }

    int edgeBlocks = (NE + 255) / 256;

    // fork: GEMM chain on s1 (graph-independent)
    cudaEventRecord(evFork, 0);
    cudaStreamWaitEvent(s1, evFork, 0);
    k_prepw<<<512, 256, 0, s1>>>(Ws1, Wn1);
    k_prepx<<<NN / 4, 256, 0, s1>>>(x);
    k_gemm2<<<dim3(4, (NN + 127) / 128), 256, GM_SMEM, s1>>>(b1);
    cudaEventRecord(evJoin, s1);

    // stream 0: CSR chain
    k_zero<<<NBLK, 256>>>();
    k_hist<<<edgeBlocks, 256>>>(dst);
    k_scanA<<<NBLK, 256>>>();
    k_scanC<<<NBLK, 256>>>();
    k_scatter<<<edgeBlocks, 256>>>(src, dst);

    // join, then fused: mean(y_src) + z -> sigmoid -> p,q
    cudaStreamWaitEvent(0, evJoin, 0);
    k_fused<<<(NN + 7) / 8, 256>>>(Ws2, Wn2);

    // layer 2: scalar mean-aggregate + combine
    k_agg_scalar<<<NBLK, 256>>>(b2, out);
}

// round 16
// speedup vs baseline: 1.0602x; 1.0602x over previous
#include <cuda_runtime.h>
#include <cuda_fp16.h>
#include <math.h>
#include <stdint.h>

#define NN 100000
#define NE 1600000
#define DF 256
#define NBLK ((NN + 255) / 256)   // 391

// ---------------- scratch (static device globals; no allocation) ----------------
__device__ int   g_deg[NN];
__device__ float g_invdeg[NN];
__device__ int   g_rowptr[NN + 1];
__device__ int   g_cursor[NN];
__device__ int   g_blksum[512];
__device__ int   g_esrc[NE];
__device__ float g_p[NN];
__device__ float g_q[NN];
__device__ __align__(16) __half g_zy[(size_t)NN * 512];   // [z(256) | y(256)] fp16 per node
__device__ __align__(16) __half g_x[(size_t)NN * DF];     // x fp16
__device__ __align__(16) __half g_wt[256 * 512];          // [K=256][N=512] = [Ws1 | Wn1] fp16

// ---------------- helpers ----------------
__device__ __forceinline__ uint32_t s2u(const void* p) {
    uint32_t a;
    asm("{ .reg .u64 t; cvta.to.shared.u64 t, %1; cvt.u32.u64 %0, t; }"
        : "=r"(a) : "l"(p));
    return a;
}

__device__ __forceinline__ void cpa16(uint32_t dst, const void* src) {
    asm volatile("cp.async.cg.shared.global [%0], [%1], 16;" :: "r"(dst), "l"(src));
}
#define CP_COMMIT() asm volatile("cp.async.commit_group;" ::: "memory")
#define CP_WAIT2()  asm volatile("cp.async.wait_group 2;" ::: "memory")
#define CP_WAIT1()  asm volatile("cp.async.wait_group 1;" ::: "memory")
#define CP_WAIT0()  asm volatile("cp.async.wait_group 0;" ::: "memory")

#define LDSM4(r, addr) \
    asm volatile("ldmatrix.sync.aligned.m8n8.x4.shared.b16 {%0,%1,%2,%3}, [%4];" \
        : "=r"((r)[0]), "=r"((r)[1]), "=r"((r)[2]), "=r"((r)[3]) : "r"(addr))

#define LDSM4T(r, addr) \
    asm volatile("ldmatrix.sync.aligned.m8n8.x4.trans.shared.b16 {%0,%1,%2,%3}, [%4];" \
        : "=r"((r)[0]), "=r"((r)[1]), "=r"((r)[2]), "=r"((r)[3]) : "r"(addr))

__device__ __forceinline__ void mma_f16(float* c, const uint32_t* a, const uint32_t* b) {
    asm volatile(
        "mma.sync.aligned.m16n8k16.row.col.f32.f16.f16.f32 "
        "{%0,%1,%2,%3}, {%4,%5,%6,%7}, {%8,%9}, {%0,%1,%2,%3};"
        : "+f"(c[0]), "+f"(c[1]), "+f"(c[2]), "+f"(c[3])
        : "r"(a[0]), "r"(a[1]), "r"(a[2]), "r"(a[3]), "r"(b[0]), "r"(b[1]));
}

// ---------------- zero deg (stream 0, before hist) ----------------
__global__ void k_zero() {
    int i = blockIdx.x * 256 + threadIdx.x;
    if (i < NN) g_deg[i] = 0;
}

// ---------------- X -> fp16 ----------------
__global__ void k_prepx(const float* __restrict__ x) {
    int gi = blockIdx.x * 256 + threadIdx.x;        // NN*64 threads, 4 floats each
    float4 v = ((const float4*)x)[gi];
    uint2 o;
    __half2 p0 = __floats2half2_rn(v.x, v.y);
    __half2 p1 = __floats2half2_rn(v.z, v.w);
    o.x = *reinterpret_cast<uint32_t*>(&p0);
    o.y = *reinterpret_cast<uint32_t*>(&p1);
    ((uint2*)g_x)[gi] = o;
}

// ---------------- weights -> fp16 [K=256][N=512] = [Ws1 | Wn1] ----------------
__global__ void k_prepw(const float* __restrict__ Ws, const float* __restrict__ Wn) {
    int idx = blockIdx.x * 256 + threadIdx.x;   // 512 blocks -> 131072
    int k = idx >> 9;
    int n = idx & 511;
    float w = (n < 256) ? Ws[(size_t)k * 256 + n] : Wn[(size_t)k * 256 + (n - 256)];
    g_wt[idx] = __float2half_rn(w);
}

// ---------------- CSR build ----------------
__global__ void k_hist(const int* __restrict__ dst) {
    int e = blockIdx.x * 256 + threadIdx.x;
    if (e < NE) atomicAdd(&g_deg[dst[e]], 1);
}

__global__ void k_scanA() {
    __shared__ int sh[256];
    int b = blockIdx.x, t = threadIdx.x;
    int i = b * 256 + t;
    int v = (i < NN) ? g_deg[i] : 0;
    sh[t] = v;
    __syncthreads();
#pragma unroll
    for (int o = 1; o < 256; o <<= 1) {
        int x = (t >= o) ? sh[t - o] : 0;
        __syncthreads();
        sh[t] += x;
        __syncthreads();
    }
    if (i < NN) g_rowptr[i] = sh[t] - v;
    if (t == 255) g_blksum[b] = sh[255];
}

// scanC with inlined block-sum prefix (replaces scanB+scanC)
__global__ void k_scanC() {
    __shared__ int red[256];
    int b = blockIdx.x, t = threadIdx.x;

    // sum of g_blksum[0..b-1]
    int part = 0;
    for (int j = t; j < b; j += 256) part += g_blksum[j];
    red[t] = part;
    __syncthreads();
#pragma unroll
    for (int o = 128; o > 0; o >>= 1) {
        if (t < o) red[t] += red[t + o];
        __syncthreads();
    }
    int off = red[0];

    int i = b * 256 + t;
    if (i < NN) {
        int r = g_rowptr[i] + off;
        g_rowptr[i] = r;
        g_cursor[i] = r;
        int d = g_deg[i];
        g_invdeg[i] = 1.0f / (float)(d > 1 ? d : 1);
    }
    if (i == 0) g_rowptr[NN] = NE;
}

__global__ void k_scatter(const int* __restrict__ src, const int* __restrict__ dst) {
    int e = blockIdx.x * 256 + threadIdx.x;
    if (e < NE) {
        int d = dst[e];
        int p = atomicAdd(&g_cursor[d], 1);
        g_esrc[p] = src[e];
    }
}

// ---------------- GEMM: [z|y] = x @ [Ws1|Wn1] (+b1 on z), fp16 in/out ----------------
// tile 128(M) x 128(N), K=256 in 8 chunks of 32; 3-stage cp.async; grid (4, 782)
#define AST 40    // As row stride (fp16 elems)
#define BST 136   // Bs row stride (fp16 elems)
#define OFF_A 0
#define OFF_B 10240
#define ST_BYTES 18944
#define GM_SMEM (3 * ST_BYTES + 512)   // 57344

__global__ __launch_bounds__(256) void k_gemm2(const float* __restrict__ bias) {
    extern __shared__ char dsm[];
    uint32_t sbase = s2u(dsm);
    float* sbb = (float*)(dsm + 3 * ST_BYTES);

    int tid = threadIdx.x;
    int wid = tid >> 5, lane = tid & 31;
    int brow = blockIdx.y * 128;
    int bcol = blockIdx.x * 128;
    int wm = wid & 3, wn = wid >> 2;

    if (tid < 128)
        sbb[tid] = (bcol < 256) ? __ldg(bias + bcol + tid) : 0.f;

    float c[2][8][4];
#pragma unroll
    for (int mt = 0; mt < 2; ++mt)
#pragma unroll
        for (int nt = 0; nt < 8; ++nt)
#pragma unroll
            for (int j = 0; j < 4; ++j) c[mt][nt][j] = 0.f;

    int arow = tid >> 1;            // 0..127
    int ak   = (tid & 1) * 16;      // halves
    int grow = brow + arow;
    if (grow >= NN) grow = NN - 1;
    int bkr = tid >> 3;             // 0..31
    int bnc = (tid & 7) * 16;       // halves

    uint32_t da = OFF_A + (uint32_t)(arow * AST + ak) * 2;
    uint32_t db = OFF_B + (uint32_t)(bkr * BST + bnc) * 2;

    auto issue = [&](int ch, int s) {
        int ka = ch * 32;
        uint32_t st = sbase + (uint32_t)s * ST_BYTES;
        size_t aoff = (size_t)grow * 256 + ka + ak;
        cpa16(st + da,      g_x + aoff);
        cpa16(st + da + 16, g_x + aoff + 8);
        size_t boff = (size_t)(ka + bkr) * 512 + bcol + bnc;
        cpa16(st + db,      g_wt + boff);
        cpa16(st + db + 16, g_wt + boff + 8);
        CP_COMMIT();
    };

    issue(0, 0);
    issue(1, 1);
    issue(2, 2);

#pragma unroll 1
    for (int ch = 0; ch < 8; ++ch) {
        if (ch < 6) CP_WAIT2();
        else if (ch == 6) CP_WAIT1();
        else CP_WAIT0();
        __syncthreads();

        uint32_t st = sbase + (uint32_t)(ch % 3) * ST_BYTES;
        uint32_t ab = st + OFF_A, bb = st + OFF_B;

#pragma unroll
        for (int ks = 0; ks < 2; ++ks) {
            int kk = ks * 16;
            uint32_t af[2][4];
#pragma unroll
            for (int mt = 0; mt < 2; ++mt) {
                int m0 = wm * 32 + mt * 16;
                uint32_t ao = (uint32_t)((m0 + (lane & 15)) * AST + kk + (lane >> 4) * 8) * 2;
                LDSM4(af[mt], ab + ao);
            }
            uint32_t bf[8][2];
#pragma unroll
            for (int nq = 0; nq < 4; ++nq) {
                int n0 = wn * 64 + nq * 16;
                uint32_t bo = (uint32_t)((kk + (lane & 15)) * BST + n0 + (lane >> 4) * 8) * 2;
                uint32_t r[4];
                LDSM4T(r, bb + bo);
                bf[nq * 2][0] = r[0]; bf[nq * 2][1] = r[1];
                bf[nq * 2 + 1][0] = r[2]; bf[nq * 2 + 1][1] = r[3];
            }
#pragma unroll
            for (int mt = 0; mt < 2; ++mt)
#pragma unroll
                for (int nt = 0; nt < 8; ++nt)
                    mma_f16(c[mt][nt], af[mt], bf[nt]);
        }

        __syncthreads();
        if (ch + 3 < 8) issue(ch + 3, ch % 3);
    }

    // epilogue: +bias (z half only), fp16 store to g_zy
#pragma unroll
    for (int mt = 0; mt < 2; ++mt) {
#pragma unroll
        for (int rh = 0; rh < 2; ++rh) {
            int row = brow + wm * 32 + mt * 16 + (lane >> 2) + rh * 8;
            if (row >= NN) continue;
#pragma unroll
            for (int nt = 0; nt < 8; ++nt) {
                int lcol = wn * 64 + nt * 8 + (lane & 3) * 2;
                float v0 = c[mt][nt][rh * 2 + 0] + sbb[lcol];
                float v1 = c[mt][nt][rh * 2 + 1] + sbb[lcol + 1];
                __half2 hv = __floats2half2_rn(v0, v1);
                *(__half2*)(g_zy + (size_t)row * 512 + bcol + lcol) = hv;
            }
        }
    }
}

// ---------------- fused: mean-gather(y fp16) + z + sigmoid + layer-2 dots ----------------
__global__ __launch_bounds__(256) void k_fused(const float* __restrict__ Ws2,
                                               const float* __restrict__ Wn2) {
    __shared__ float sw[256], sn[256];
    int t = threadIdx.x;
    sw[t] = Ws2[t];
    sn[t] = Wn2[t];
    __syncthreads();

    int warp = t >> 5, lane = t & 31;
    int node = blockIdx.x * 8 + warp;
    if (node >= NN) return;

    int beg = g_rowptr[node];
    int end = g_rowptr[node + 1];
    int c0 = lane * 8;

    float acc[8];
#pragma unroll
    for (int i = 0; i < 8; ++i) acc[i] = 0.f;

    const __half* Y = g_zy;
    int e = beg;
    for (; e + 1 < end; e += 2) {
        int s0 = g_esrc[e];
        int s1 = g_esrc[e + 1];
        uint4 u0 = *(const uint4*)(Y + (size_t)s0 * 512 + 256 + c0);
        uint4 u1 = *(const uint4*)(Y + (size_t)s1 * 512 + 256 + c0);
        const __half2* p0 = (const __half2*)&u0;
        const __half2* p1 = (const __half2*)&u1;
#pragma unroll
        for (int i = 0; i < 4; ++i) {
            float2 f0 = __half22float2(p0[i]);
            float2 f1 = __half22float2(p1[i]);
            acc[i * 2]     += f0.x + f1.x;
            acc[i * 2 + 1] += f0.y + f1.y;
        }
    }
    if (e < end) {
        int s0 = g_esrc[e];
        uint4 u0 = *(const uint4*)(Y + (size_t)s0 * 512 + 256 + c0);
        const __half2* p0 = (const __half2*)&u0;
#pragma unroll
        for (int i = 0; i < 4; ++i) {
            float2 f0 = __half22float2(p0[i]);
            acc[i * 2]     += f0.x;
            acc[i * 2 + 1] += f0.y;
        }
    }

    float id = g_invdeg[node];
    uint4 uz = *(const uint4*)(Y + (size_t)node * 512 + c0);
    const __half2* pz = (const __half2*)&uz;

    float q = 0.f, p = 0.f;
#pragma unroll
    for (int i = 0; i < 4; ++i) {
        float2 z = __half22float2(pz[i]);
        float v0 = z.x + acc[i * 2] * id;
        float v1 = z.y + acc[i * 2 + 1] * id;
        float h0 = 1.f / (1.f + __expf(-v0));
        float h1 = 1.f / (1.f + __expf(-v1));
        q += h0 * sw[c0 + i * 2] + h1 * sw[c0 + i * 2 + 1];
        p += h0 * sn[c0 + i * 2] + h1 * sn[c0 + i * 2 + 1];
    }
#pragma unroll
    for (int o = 16; o > 0; o >>= 1) {
        q += __shfl_down_sync(0xffffffffu, q, o);
        p += __shfl_down_sync(0xffffffffu, p, o);
    }
    if (lane == 0) {
        g_q[node] = q;
        g_p[node] = p;
    }
}

// ---------------- layer 2b: scalar mean-aggregate + combine ----------------
__global__ void k_agg_scalar(const float* __restrict__ b2, float* __restrict__ out) {
    int n = blockIdx.x * 256 + threadIdx.x;
    if (n >= NN) return;
    int beg = g_rowptr[n];
    int end = g_rowptr[n + 1];
    float s0 = 0.f, s1 = 0.f, s2 = 0.f, s3 = 0.f;
    int e = beg;
    for (; e + 3 < end; e += 4) {
        s0 += g_p[g_esrc[e]];
        s1 += g_p[g_esrc[e + 1]];
        s2 += g_p[g_esrc[e + 2]];
        s3 += g_p[g_esrc[e + 3]];
    }
    for (; e < end; ++e) s0 += g_p[g_esrc[e]];
    float s = (s0 + s1) + (s2 + s3);
    out[n] = g_q[n] + b2[0] + s * g_invdeg[n];
}

// ---------------- launch ----------------
extern "C" void kernel_launch(void* const* d_in, const int* in_sizes, int n_in,
                              void* d_out, int out_size) {
    const float* x   = (const float*)d_in[0];
    const int*   src = (const int*)d_in[1];
    const int*   dst = (const int*)d_in[2];
    const float* Ws1 = (const float*)d_in[3];
    const float* Wn1 = (const float*)d_in[4];
    const float* b1  = (const float*)d_in[5];
    const float* Ws2 = (const float*)d_in[6];
    const float* Wn2 = (const float*)d_in[7];
    const float* b2  = (const float*)d_in[8];
    float* out = (float*)d_out;

    static cudaStream_t s1 = nullptr;
    static cudaEvent_t evFork = nullptr, evJoin = nullptr;
    if (!s1) {
        cudaStreamCreateWithFlags(&s1, cudaStreamNonBlocking);
        cudaEventCreateWithFlags(&evFork, cudaEventDisableTiming);
        cudaEventCreateWithFlags(&evJoin, cudaEventDisableTiming);
        cudaFuncSetAttribute(k_gemm2, cudaFuncAttributeMaxDynamicSharedMemorySize, GM_SMEM);
    }

    int edgeBlocks = (NE + 255) / 256;

    // fork: GEMM chain on s1 (graph-independent)
    cudaEventRecord(evFork, 0);
    cudaStreamWaitEvent(s1, evFork, 0);
    k_prepw<<<512, 256, 0, s1>>>(Ws1, Wn1);
    k_prepx<<<NN / 4, 256, 0, s1>>>(x);
    k_gemm2<<<dim3(4, (NN + 127) / 128), 256, GM_SMEM, s1>>>(b1);
    cudaEventRecord(evJoin, s1);

    // stream 0: CSR chain
    k_zero<<<NBLK, 256>>>();
    k_hist<<<edgeBlocks, 256>>>(dst);
    k_scanA<<<NBLK, 256>>>();
    k_scanC<<<NBLK, 256>>>();
    k_scatter<<<edgeBlocks, 256>>>(src, dst);

    // join, then fused: mean(y_src) + z -> sigmoid -> p,q
    cudaStreamWaitEvent(0, evJoin, 0);
    k_fused<<<(NN + 7) / 8, 256>>>(Ws2, Wn2);

    // layer 2: scalar mean-aggregate + combine
    k_agg_scalar<<<NBLK, 256>>>(b2, out);
}